// round 13
// baseline (speedup 1.0000x reference)
#include <cuda_runtime.h>
#include <cstdint>

// ---------------- problem constants ----------------
#define M_NODES 50000
#define E_EDGES 600000
#define IN_CH   300
#define HID     128
#define NGRAPH  128
#define NF      (M_NODES * HID)   // 6,400,000
#define WPK_TOT 71680
#define SBLK    256
#define NBLK    ((M_NODES + SBLK - 1) / SBLK)   // 196

// ---------------- scratch (static device memory; no allocs) ----------------
__device__ __align__(16) float g_scratch[3 * NF + 256 + 16384 + 128 + 256 + M_NODES
                                         + 2 * WPK_TOT + 2 * M_NODES + E_EDGES + NBLK + 64];

// ---------------- helpers ----------------
__device__ __forceinline__ void red_add_v4(float* addr, float4 v) {
    asm volatile("red.global.add.v4.f32 [%0], {%1, %2, %3, %4};"
                 :: "l"(addr), "f"(v.x), "f"(v.y), "f"(v.z), "f"(v.w) : "memory");
}
__device__ __forceinline__ void red_add_v2(float* addr, float a, float b) {
    asm volatile("red.global.add.v2.f32 [%0], {%1, %2};"
                 :: "l"(addr), "f"(a), "f"(b) : "memory");
}
__device__ __forceinline__ uint32_t pkbf(float lo, float hi) {
    uint32_t r;
    asm("cvt.rn.bf16x2.f32 %0, %1, %2;" : "=r"(r) : "f"(hi), "f"(lo));
    return r;
}
__device__ __forceinline__ float bflo(uint32_t p) { return __uint_as_float(p << 16); }
__device__ __forceinline__ float bfhi(uint32_t p) { return __uint_as_float(p & 0xFFFF0000u); }

__device__ __forceinline__ void mma_bf16(float c[4],
                                         uint32_t a0, uint32_t a1, uint32_t a2, uint32_t a3,
                                         uint32_t b0, uint32_t b1) {
    asm volatile(
        "mma.sync.aligned.m16n8k16.row.col.f32.bf16.bf16.f32 "
        "{%0,%1,%2,%3}, {%4,%5,%6,%7}, {%8,%9}, {%0,%1,%2,%3};"
        : "+f"(c[0]), "+f"(c[1]), "+f"(c[2]), "+f"(c[3])
        : "r"(a0), "r"(a1), "r"(a2), "r"(a3), "r"(b0), "r"(b1));
}
__device__ __forceinline__ uint32_t smem_u32(const void* p) {
    uint32_t a;
    asm("{ .reg .u64 t; cvta.to.shared.u64 t, %1; cvt.u32.u64 %0, t; }" : "=r"(a) : "l"(p));
    return a;
}
__device__ __forceinline__ void cp_async16(uint32_t dst, const void* src, int nb) {
    asm volatile("cp.async.cg.shared.global [%0], [%1], 16, %2;"
                 :: "r"(dst), "l"(src), "r"(nb) : "memory");
}
__device__ __forceinline__ void cp_commit() { asm volatile("cp.async.commit_group;" ::: "memory"); }
__device__ __forceinline__ void cp_wait2()  { asm volatile("cp.async.wait_group 2;" ::: "memory"); }
__device__ __forceinline__ void cp_wait1()  { asm volatile("cp.async.wait_group 1;" ::: "memory"); }
__device__ __forceinline__ void cp_wait0()  { asm volatile("cp.async.wait_group 0;" ::: "memory"); }

// ---------------- split ALL weights once ----------------
__global__ void split_w_all(const float* __restrict__ W0, const float* __restrict__ W1,
                            const float* __restrict__ W2, const float* __restrict__ W3,
                            const float* __restrict__ W4, const float* __restrict__ W5,
                            uint32_t* __restrict__ Wh, uint32_t* __restrict__ Wl)
{
    int i = blockIdx.x * blockDim.x + threadIdx.x;
    if (i >= WPK_TOT) return;
    const float* W;
    int base, K, K2pad;
    if      (i < 19456) { W = W0; base = 0;     K = 300; K2pad = 152; }
    else if (i < 38912) { W = W1; base = 19456; K = 300; K2pad = 152; }
    else if (i < 47104) { W = W2; base = 38912; K = 128; K2pad = 64; }
    else if (i < 55296) { W = W3; base = 47104; K = 128; K2pad = 64; }
    else if (i < 63488) { W = W4; base = 55296; K = 128; K2pad = 64; }
    else                { W = W5; base = 63488; K = 128; K2pad = 64; }
    int j = i - base;
    int n = j / K2pad, k2 = j % K2pad;
    float w0 = (2 * k2     < K) ? W[(size_t)(2 * k2)     * HID + n] : 0.f;
    float w1 = (2 * k2 + 1 < K) ? W[(size_t)(2 * k2 + 1) * HID + n] : 0.f;
    uint32_t hh = pkbf(w0, w1);
    Wh[i] = hh;
    Wl[i] = pkbf(w0 - bflo(hh), w1 - bfhi(hh));
}

// ---------------- 3-stage pipelined BF16x3 GEMM with fused scatter ----------------
// grid.y == 0: xl tile = op(A)@W0 kept in SMEM, then warp-per-row CSR scatter:
//              h[dst] += xl[src]*invdeg[dst]  (red.v4)
// grid.y == 1: h += op(A)@W1 + bias           (red.v2; h pre-zeroed)
#define LDA   24
#define BNP   12
#define LDX   132   // smem xl tile row stride (floats)
#define BUF_BYTES (128 * LDA * 4 + 2 * 128 * BNP * 4)   // 24576
#define AOFF(b)  ((b) * BUF_BYTES)
#define BHOFF(b) ((b) * BUF_BYTES + 128 * LDA * 4)
#define BLOFF(b) ((b) * BUF_BYTES + 128 * LDA * 4 + 128 * BNP * 4)
#define SMEM_TOT (3 * BUF_BYTES)                        // 73728 >= 128*LDX*4 = 67584

__global__ void __launch_bounds__(256, 2)
gemm_bf16_fused(const float* __restrict__ A,
                const uint32_t* __restrict__ Bh0, const uint32_t* __restrict__ Bl0,
                const uint32_t* __restrict__ Bh1, const uint32_t* __restrict__ Bl1,
                float* __restrict__ h,
                const float* __restrict__ bias,
                const float* __restrict__ scale, const float* __restrict__ shift,
                const int* __restrict__ rowptr, const int* __restrict__ csrdst,
                const float* __restrict__ invdeg,
                int M, int K, int K2pad)
{
    extern __shared__ char smem[];
    const uint32_t sb = smem_u32(smem);

    const uint32_t* BhG = blockIdx.y ? Bh1 : Bh0;
    const uint32_t* BlG = blockIdx.y ? Bl1 : Bl0;
    const int mBase = blockIdx.x * 128;

    const int tid  = threadIdx.x;
    const int wid  = tid >> 5;
    const int lane = tid & 31;
    const int quad = lane >> 2;
    const int tq   = lane & 3;
    const int m0   = (wid & 3) * 32;
    const int n0   = (wid >> 2) * 64;
    const bool bn  = (scale != nullptr);

    const int ar0 = tid >> 2, ac0 = (tid & 3) * 4;
    const int ar1 = (tid + 256) >> 2, ac1 = ac0;
    const int bn_row = tid >> 1, bn_ch = (tid & 1) * 4;

    float acc[2][8][4];
    #pragma unroll
    for (int i = 0; i < 2; i++)
        #pragma unroll
        for (int j = 0; j < 8; j++)
            #pragma unroll
            for (int q = 0; q < 4; q++) acc[i][j][q] = 0.f;

    const int nT = (K + 15) / 16;

    auto issue_tile = [&](int t, int buf) {
        const int k0 = t * 16;
        {
            int gr = mBase + ar0;
            const float* src = A + (size_t)gr * K + k0 + ac0;
            int nb = (gr < M && (k0 + ac0) < K) ? 16 : 0;
            if (!nb) src = A;
            cp_async16(sb + AOFF(buf) + (ar0 * LDA + ac0) * 4, src, nb);
        }
        {
            int gr = mBase + ar1;
            const float* src = A + (size_t)gr * K + k0 + ac1;
            int nb = (gr < M && (k0 + ac1) < K) ? 16 : 0;
            if (!nb) src = A;
            cp_async16(sb + AOFF(buf) + (ar1 * LDA + ac1) * 4, src, nb);
        }
        {
            const uint32_t* srcH = BhG + (size_t)bn_row * K2pad + t * 8 + bn_ch;
            const uint32_t* srcL = BlG + (size_t)bn_row * K2pad + t * 8 + bn_ch;
            uint32_t d = (bn_row * BNP + bn_ch) * 4;
            cp_async16(sb + BHOFF(buf) + d, srcH, 16);
            cp_async16(sb + BLOFF(buf) + d, srcL, 16);
        }
        cp_commit();
    };

    issue_tile(0, 0);
    if (nT > 1) issue_tile(1, 1);

    for (int t = 0; t < nT; t++) {
        const int buf = t % 3;
        if (t + 2 < nT) {
            issue_tile(t + 2, (t + 2) % 3);
            cp_wait2();
        } else if (t + 1 < nT) {
            cp_wait1();
        } else {
            cp_wait0();
        }
        __syncthreads();

        const float* Ab = reinterpret_cast<const float*>(smem + AOFF(buf));
        const uint32_t* Bhb = reinterpret_cast<const uint32_t*>(smem + BHOFF(buf));
        const uint32_t* Blb = reinterpret_cast<const uint32_t*>(smem + BLOFF(buf));
        const int k0 = t * 16;

        float2 scA = make_float2(1.f, 1.f), shA = make_float2(0.f, 0.f);
        float2 scB = make_float2(1.f, 1.f), shB = make_float2(0.f, 0.f);
        if (bn) {
            scA = *reinterpret_cast<const float2*>(scale + k0 + 2 * tq);
            shA = *reinterpret_cast<const float2*>(shift + k0 + 2 * tq);
            scB = *reinterpret_cast<const float2*>(scale + k0 + 2 * tq + 8);
            shB = *reinterpret_cast<const float2*>(shift + k0 + 2 * tq + 8);
        }

        uint32_t ah[2][4], al[2][4];
        #pragma unroll
        for (int mi = 0; mi < 2; mi++) {
            int mr = m0 + mi * 16 + quad;
            float2 p0 = *reinterpret_cast<const float2*>(Ab + mr * LDA + 2 * tq);
            float2 p1 = *reinterpret_cast<const float2*>(Ab + (mr + 8) * LDA + 2 * tq);
            float2 p2 = *reinterpret_cast<const float2*>(Ab + mr * LDA + 2 * tq + 8);
            float2 p3 = *reinterpret_cast<const float2*>(Ab + (mr + 8) * LDA + 2 * tq + 8);
            if (bn) {
                p0.x = fmaxf(fmaf(p0.x, scA.x, shA.x), 0.f);
                p0.y = fmaxf(fmaf(p0.y, scA.y, shA.y), 0.f);
                p1.x = fmaxf(fmaf(p1.x, scA.x, shA.x), 0.f);
                p1.y = fmaxf(fmaf(p1.y, scA.y, shA.y), 0.f);
                p2.x = fmaxf(fmaf(p2.x, scB.x, shB.x), 0.f);
                p2.y = fmaxf(fmaf(p2.y, scB.y, shB.y), 0.f);
                p3.x = fmaxf(fmaf(p3.x, scB.x, shB.x), 0.f);
                p3.y = fmaxf(fmaf(p3.y, scB.y, shB.y), 0.f);
            }
            ah[mi][0] = pkbf(p0.x, p0.y);
            al[mi][0] = pkbf(p0.x - bflo(ah[mi][0]), p0.y - bfhi(ah[mi][0]));
            ah[mi][1] = pkbf(p1.x, p1.y);
            al[mi][1] = pkbf(p1.x - bflo(ah[mi][1]), p1.y - bfhi(ah[mi][1]));
            ah[mi][2] = pkbf(p2.x, p2.y);
            al[mi][2] = pkbf(p2.x - bflo(ah[mi][2]), p2.y - bfhi(ah[mi][2]));
            ah[mi][3] = pkbf(p3.x, p3.y);
            al[mi][3] = pkbf(p3.x - bflo(ah[mi][3]), p3.y - bfhi(ah[mi][3]));
        }

        #pragma unroll
        for (int ni = 0; ni < 8; ni++) {
            int nc = n0 + ni * 8 + quad;
            uint32_t bh0 = Bhb[nc * BNP + tq];
            uint32_t bh1 = Bhb[nc * BNP + tq + 4];
            uint32_t bl0 = Blb[nc * BNP + tq];
            uint32_t bl1 = Blb[nc * BNP + tq + 4];
            #pragma unroll
            for (int mi = 0; mi < 2; mi++) {
                mma_bf16(acc[mi][ni], ah[mi][0], ah[mi][1], ah[mi][2], ah[mi][3], bh0, bh1);
                mma_bf16(acc[mi][ni], ah[mi][0], ah[mi][1], ah[mi][2], ah[mi][3], bl0, bl1);
                mma_bf16(acc[mi][ni], al[mi][0], al[mi][1], al[mi][2], al[mi][3], bh0, bh1);
            }
        }
        __syncthreads();
    }

    if (blockIdx.y == 0) {
        // ---- xl tile -> SMEM (reuse pipeline buffers), then CSR scatter ----
        float* xs = reinterpret_cast<float*>(smem);
        #pragma unroll
        for (int mi = 0; mi < 2; mi++) {
            int r0 = m0 + mi * 16 + quad;
            #pragma unroll
            for (int ni = 0; ni < 8; ni++) {
                int col = n0 + ni * 8 + tq * 2;
                *reinterpret_cast<float2*>(xs + r0 * LDX + col) =
                    make_float2(acc[mi][ni][0], acc[mi][ni][1]);
                *reinterpret_cast<float2*>(xs + (r0 + 8) * LDX + col) =
                    make_float2(acc[mi][ni][2], acc[mi][ni][3]);
            }
        }
        __syncthreads();
        // warp-per-row scatter: warp wid handles rows [wid*16, wid*16+16)
        for (int rl = wid * 16; rl < wid * 16 + 16; rl++) {
            int gr = mBase + rl;
            if (gr >= M) break;
            int rs = rowptr[gr], re = rowptr[gr + 1];
            if (rs == re) continue;
            float4 v = *reinterpret_cast<const float4*>(xs + rl * LDX + lane * 4);
            for (int e = rs; e < re; e++) {
                int d = csrdst[e];
                float inv = invdeg[d];
                float4 w = make_float4(v.x * inv, v.y * inv, v.z * inv, v.w * inv);
                red_add_v4(h + (size_t)d * HID + lane * 4, w);
            }
        }
    } else {
        // ---- self path: h += acc + bias (atomic, h pre-zeroed) ----
        #pragma unroll
        for (int mi = 0; mi < 2; mi++) {
            int r0 = mBase + m0 + mi * 16 + quad;
            #pragma unroll
            for (int ni = 0; ni < 8; ni++) {
                int col = n0 + ni * 8 + tq * 2;
                float2 bb = *reinterpret_cast<const float2*>(bias + col);
                if (r0 < M)
                    red_add_v2(h + (size_t)r0 * HID + col,
                               acc[mi][ni][0] + bb.x, acc[mi][ni][1] + bb.y);
                if (r0 + 8 < M)
                    red_add_v2(h + (size_t)(r0 + 8) * HID + col,
                               acc[mi][ni][2] + bb.x, acc[mi][ni][3] + bb.y);
            }
        }
    }
}

// ---------------- zero kernel ----------------
__global__ void zero4_kernel(float4* __restrict__ p, int n4) {
    int i = blockIdx.x * blockDim.x + threadIdx.x;
    if (i < n4) p[i] = make_float4(0.f, 0.f, 0.f, 0.f);
}

// ---------------- fused dst-degree + src-histogram ----------------
__global__ void deg_hist_kernel(const int* __restrict__ ei, float* __restrict__ deg,
                                int* __restrict__ counts, int E) {
    int e = blockIdx.x * blockDim.x + threadIdx.x;
    if (e >= E) return;
    atomicAdd(&deg[ei[E + e]], 1.0f);
    atomicAdd(&counts[ei[e]], 1);
}
__global__ void invdeg_kernel(float* __restrict__ deg, int M) {
    int i = blockIdx.x * blockDim.x + threadIdx.x;
    if (i < M) deg[i] = 1.0f / fmaxf(deg[i], 1.0f);
}

// ---------------- src-CSR build ----------------
__global__ void blocksum_kernel(const int* __restrict__ counts, int* __restrict__ bsum, int M) {
    __shared__ int sh[SBLK];
    int i = blockIdx.x * SBLK + threadIdx.x;
    sh[threadIdx.x] = (i < M) ? counts[i] : 0;
    __syncthreads();
    for (int off = SBLK / 2; off > 0; off >>= 1) {
        if (threadIdx.x < off) sh[threadIdx.x] += sh[threadIdx.x + off];
        __syncthreads();
    }
    if (threadIdx.x == 0) bsum[blockIdx.x] = sh[0];
}
__global__ void bscan_kernel(int* __restrict__ bsum, int nb) {
    if (threadIdx.x == 0) {
        int run = 0;
        for (int i = 0; i < nb; i++) { int c = bsum[i]; bsum[i] = run; run += c; }
    }
}
__global__ void localscan_kernel(const int* __restrict__ counts, const int* __restrict__ boff,
                                 int* __restrict__ rowptr, int* __restrict__ cursor, int M) {
    __shared__ int sh[SBLK];
    int i = blockIdx.x * SBLK + threadIdx.x;
    int c = (i < M) ? counts[i] : 0;
    sh[threadIdx.x] = c;
    __syncthreads();
    for (int off = 1; off < SBLK; off <<= 1) {
        int v = (threadIdx.x >= off) ? sh[threadIdx.x - off] : 0;
        __syncthreads();
        sh[threadIdx.x] += v;
        __syncthreads();
    }
    int excl = boff[blockIdx.x] + sh[threadIdx.x] - c;
    if (i < M) { rowptr[i] = excl; cursor[i] = excl; }
    if (i == M - 1) rowptr[M] = excl + c;
}
__global__ void fill_kernel(const int* __restrict__ ei, int* __restrict__ cursor,
                            int* __restrict__ csrdst, int E) {
    int e = blockIdx.x * blockDim.x + threadIdx.x;
    if (e >= E) return;
    int s = ei[e];
    int pos = atomicAdd(&cursor[s], 1);
    csrdst[pos] = ei[E + e];
}

// ---------------- BN stats over h (optionally zero next layer's h) ----------------
#define ROWS_PB 64
__global__ void stats_kernel(const float* __restrict__ h,
                             float* __restrict__ colsum,
                             float* __restrict__ colsumsq,
                             float* __restrict__ zbuf, int M)
{
    int col = threadIdx.x;
    int r0 = blockIdx.x * ROWS_PB;
    int r1 = min(r0 + ROWS_PB, M);
    float s = 0.f, s2 = 0.f;
    for (int r = r0; r < r1; r++) {
        float v = h[(size_t)r * HID + col];
        s += v; s2 += v * v;
        if (zbuf) zbuf[(size_t)r * HID + col] = 0.f;
    }
    atomicAdd(&colsum[col], s);
    atomicAdd(&colsumsq[col], s2);
}

// ---------------- BN finalize ----------------
__global__ void bn_finalize(float* __restrict__ colsum,
                            float* __restrict__ colsumsq,
                            const float* __restrict__ gamma,
                            const float* __restrict__ beta,
                            float* __restrict__ scale,
                            float* __restrict__ shift, int M)
{
    int c = threadIdx.x;
    float invM = 1.0f / (float)M;
    float mu = colsum[c] * invM;
    float var = colsumsq[c] * invM - mu * mu;
    float rs = rsqrtf(var + 1e-5f);
    float sc = rs * gamma[c];
    scale[c] = sc;
    shift[c] = beta[c] - mu * sc;
    colsum[c] = 0.f;
    colsumsq[c] = 0.f;
}

// ---------------- pool with fused BN+relu ----------------
__global__ void pool_bn_kernel(const float* __restrict__ h,
                               const int* __restrict__ batch,
                               const float* __restrict__ scale,
                               const float* __restrict__ shift,
                               float* __restrict__ pooled,
                               float* __restrict__ cnt, int M)
{
    int warp = (blockIdx.x * blockDim.x + threadIdx.x) >> 5;
    int lane = threadIdx.x & 31;
    if (warp >= M) return;
    int g = batch[warp];
    float4 v = reinterpret_cast<const float4*>(h)[warp * 32 + lane];
    float4 sc = reinterpret_cast<const float4*>(scale)[lane];
    float4 sh = reinterpret_cast<const float4*>(shift)[lane];
    v.x = fmaxf(fmaf(v.x, sc.x, sh.x), 0.f);
    v.y = fmaxf(fmaf(v.y, sc.y, sh.y), 0.f);
    v.z = fmaxf(fmaf(v.z, sc.z, sh.z), 0.f);
    v.w = fmaxf(fmaf(v.w, sc.w, sh.w), 0.f);
    red_add_v4(pooled + (long long)g * HID + lane * 4, v);
    if (lane == 0) atomicAdd(&cnt[g], 1.0f);
}

// ---------------- head ----------------
__global__ void head_kernel(const float* __restrict__ pooled,
                            const float* __restrict__ cnt,
                            const float* __restrict__ Wc,
                            const float* __restrict__ bc,
                            float* __restrict__ out, int mode)
{
    int g = threadIdx.x;
    float c = fmaxf(cnt[g], 1.f);
    float inv = 1.0f / c;
    float a0 = bc[0], a1 = bc[1];
    float* hg_out = (mode == 0) ? (out + 2 * NGRAPH) : out;
    for (int k = 0; k < HID; k++) {
        float v = pooled[g * HID + k] * inv;
        if (mode != 1) hg_out[g * HID + k] = v;
        a0 = fmaf(v, Wc[k * 2 + 0], a0);
        a1 = fmaf(v, Wc[k * 2 + 1], a1);
    }
    if (mode != 2) {
        out[g * 2 + 0] = a0;
        out[g * 2 + 1] = a1;
    }
}

// ---------------- launcher ----------------
extern "C" void kernel_launch(void* const* d_in, const int* in_sizes, int n_in,
                              void* d_out, int out_size)
{
    const float* x     = (const float*)d_in[0];
    const int*   ei    = (const int*)d_in[1];
    const int*   batch = (const int*)d_in[2];

    const float* Wl[3] = { (const float*)d_in[3],  (const float*)d_in[8],  (const float*)d_in[13] };
    const float* Wr[3] = { (const float*)d_in[4],  (const float*)d_in[9],  (const float*)d_in[14] };
    const float* bi[3] = { (const float*)d_in[5],  (const float*)d_in[10], (const float*)d_in[15] };
    const float* ga[3] = { (const float*)d_in[6],  (const float*)d_in[11], (const float*)d_in[16] };
    const float* be[3] = { (const float*)d_in[7],  (const float*)d_in[12], (const float*)d_in[17] };
    const float* Wc = (const float*)d_in[18];
    const float* bc = (const float*)d_in[19];

    float* base = nullptr;
    cudaGetSymbolAddress((void**)&base, g_scratch);

    float* xl       = base;                   // unused now (kept for layout stability)
    float* hA       = xl + NF;
    float* hB       = hA + NF;
    float* colsum   = hB + NF;
    float* colsumsq = colsum + HID;
    float* pooled   = colsumsq + HID;
    float* cnt      = pooled + NGRAPH * HID;
    float* scale    = cnt + NGRAPH;
    float* shift    = scale + HID;
    float* invdeg   = shift + HID;
    uint32_t* Wh    = (uint32_t*)(invdeg + M_NODES);
    uint32_t* Wlo   = Wh + WPK_TOT;
    int* rowptr     = (int*)(Wlo + WPK_TOT);
    int* cursor     = rowptr + M_NODES + 4;
    int* csrdst     = cursor + M_NODES;
    int* bsum       = csrdst + E_EDGES;

    const int woff[3][2] = { {0, 19456}, {38912, 47104}, {55296, 63488} };
    const int K2p[3] = { 152, 64, 64 };

    const int M = M_NODES, E = E_EDGES;
    float* out = (float*)d_out;

    int mode = 0;
    if (out_size < 16640) mode = (out_size >= 16384) ? 2 : 1;

    cudaFuncSetAttribute(gemm_bf16_fused,
                         cudaFuncAttributeMaxDynamicSharedMemorySize, SMEM_TOT);

    // ---- setup ----
    {
        int z4 = (2 * HID + NGRAPH * HID + NGRAPH) / 4;
        zero4_kernel<<<(z4 + 255) / 256, 256>>>((float4*)colsum, z4);
        zero4_kernel<<<(NF / 4 + 255) / 256, 256>>>((float4*)hA, NF / 4);   // h pre-zero (layer 0)
        zero4_kernel<<<(M / 4 + 255) / 256, 256>>>((float4*)invdeg, M / 4);
        zero4_kernel<<<(M / 4 + 255) / 256, 256>>>((float4*)cursor, M / 4);
        deg_hist_kernel<<<(E + 255) / 256, 256>>>(ei, invdeg, cursor, E);
        invdeg_kernel<<<(M + 255) / 256, 256>>>(invdeg, M);
        blocksum_kernel<<<NBLK, SBLK>>>(cursor, bsum, M);
        bscan_kernel<<<1, 32>>>(bsum, NBLK);
        localscan_kernel<<<NBLK, SBLK>>>(cursor, bsum, rowptr, cursor, M);
        fill_kernel<<<(E + 255) / 256, 256>>>(ei, cursor, csrdst, E);
        split_w_all<<<(WPK_TOT + 255) / 256, 256>>>(Wl[0], Wr[0], Wl[1], Wr[1], Wl[2], Wr[2],
                                                    Wh, Wlo);
    }

    // ping-pong: layer0 -> hA (zeroes hB in stats), layer1 -> hB (zeroes hA), layer2 -> hA
    float* hout[3]      = { hA, hB, hA };
    const float* hin[3] = { x,  hA, hB };
    float* zb[3]        = { hB, hA, nullptr };

    int K = IN_CH;
    for (int l = 0; l < 3; l++) {
        const float* sc = (l == 0) ? nullptr : scale;
        const float* sh = (l == 0) ? nullptr : shift;

        dim3 grid((M + 127) / 128, 2);
        gemm_bf16_fused<<<grid, 256, SMEM_TOT>>>(hin[l],
                                                 Wh + woff[l][0], Wlo + woff[l][0],
                                                 Wh + woff[l][1], Wlo + woff[l][1],
                                                 hout[l], bi[l], sc, sh,
                                                 rowptr, csrdst, invdeg,
                                                 M, K, K2p[l]);

        stats_kernel<<<(M + ROWS_PB - 1) / ROWS_PB, HID>>>(hout[l], colsum, colsumsq,
                                                           zb[l], M);
        bn_finalize<<<1, HID>>>(colsum, colsumsq, ga[l], be[l], scale, shift, M);

        K = HID;
    }

    pool_bn_kernel<<<(M * 32 + 255) / 256, 256>>>(hA, batch, scale, shift, pooled, cnt, M);
    head_kernel<<<1, NGRAPH>>>(pooled, cnt, Wc, bc, out, mode);
}

// round 14
// speedup vs baseline: 1.0197x; 1.0197x over previous
#include <cuda_runtime.h>
#include <cstdint>

// ---------------- problem constants ----------------
#define M_NODES 50000
#define E_EDGES 600000
#define IN_CH   300
#define HID     128
#define NGRAPH  128
#define NF      (M_NODES * HID)   // 6,400,000
#define WPK_TOT 71680
#define SBLK    256
#define NBLK    ((M_NODES + SBLK - 1) / SBLK)   // 196

// ---------------- scratch (static device memory; no allocs) ----------------
__device__ __align__(16) float g_scratch[3 * NF + 256 + 16384 + 128 + 256 + M_NODES
                                         + 2 * WPK_TOT + 2 * M_NODES + E_EDGES + NBLK + 64];

// ---------------- helpers ----------------
__device__ __forceinline__ void red_add_v4(float* addr, float4 v) {
    asm volatile("red.global.add.v4.f32 [%0], {%1, %2, %3, %4};"
                 :: "l"(addr), "f"(v.x), "f"(v.y), "f"(v.z), "f"(v.w) : "memory");
}
__device__ __forceinline__ uint32_t pkbf(float lo, float hi) {
    uint32_t r;
    asm("cvt.rn.bf16x2.f32 %0, %1, %2;" : "=r"(r) : "f"(hi), "f"(lo));
    return r;
}
__device__ __forceinline__ float bflo(uint32_t p) { return __uint_as_float(p << 16); }
__device__ __forceinline__ float bfhi(uint32_t p) { return __uint_as_float(p & 0xFFFF0000u); }

__device__ __forceinline__ void mma_bf16(float c[4],
                                         uint32_t a0, uint32_t a1, uint32_t a2, uint32_t a3,
                                         uint32_t b0, uint32_t b1) {
    asm volatile(
        "mma.sync.aligned.m16n8k16.row.col.f32.bf16.bf16.f32 "
        "{%0,%1,%2,%3}, {%4,%5,%6,%7}, {%8,%9}, {%0,%1,%2,%3};"
        : "+f"(c[0]), "+f"(c[1]), "+f"(c[2]), "+f"(c[3])
        : "r"(a0), "r"(a1), "r"(a2), "r"(a3), "r"(b0), "r"(b1));
}
__device__ __forceinline__ uint32_t smem_u32(const void* p) {
    uint32_t a;
    asm("{ .reg .u64 t; cvta.to.shared.u64 t, %1; cvt.u32.u64 %0, t; }" : "=r"(a) : "l"(p));
    return a;
}
__device__ __forceinline__ void cp_async16(uint32_t dst, const void* src, int nb) {
    asm volatile("cp.async.cg.shared.global [%0], [%1], 16, %2;"
                 :: "r"(dst), "l"(src), "r"(nb) : "memory");
}
__device__ __forceinline__ void cp_commit() { asm volatile("cp.async.commit_group;" ::: "memory"); }
__device__ __forceinline__ void cp_wait2()  { asm volatile("cp.async.wait_group 2;" ::: "memory"); }
__device__ __forceinline__ void cp_wait1()  { asm volatile("cp.async.wait_group 1;" ::: "memory"); }
__device__ __forceinline__ void cp_wait0()  { asm volatile("cp.async.wait_group 0;" ::: "memory"); }

// ---------------- split ALL weights once ----------------
__global__ void split_w_all(const float* __restrict__ W0, const float* __restrict__ W1,
                            const float* __restrict__ W2, const float* __restrict__ W3,
                            const float* __restrict__ W4, const float* __restrict__ W5,
                            uint32_t* __restrict__ Wh, uint32_t* __restrict__ Wl)
{
    int i = blockIdx.x * blockDim.x + threadIdx.x;
    if (i >= WPK_TOT) return;
    const float* W;
    int base, K, K2pad;
    if      (i < 19456) { W = W0; base = 0;     K = 300; K2pad = 152; }
    else if (i < 38912) { W = W1; base = 19456; K = 300; K2pad = 152; }
    else if (i < 47104) { W = W2; base = 38912; K = 128; K2pad = 64; }
    else if (i < 55296) { W = W3; base = 47104; K = 128; K2pad = 64; }
    else if (i < 63488) { W = W4; base = 55296; K = 128; K2pad = 64; }
    else                { W = W5; base = 63488; K = 128; K2pad = 64; }
    int j = i - base;
    int n = j / K2pad, k2 = j % K2pad;
    float w0 = (2 * k2     < K) ? W[(size_t)(2 * k2)     * HID + n] : 0.f;
    float w1 = (2 * k2 + 1 < K) ? W[(size_t)(2 * k2 + 1) * HID + n] : 0.f;
    uint32_t hh = pkbf(w0, w1);
    Wh[i] = hh;
    Wl[i] = pkbf(w0 - bflo(hh), w1 - bfhi(hh));
}

// ---------------- 3-stage pipelined BF16x3 tensor GEMM ----------------
#define LDA   24
#define BNP   12
#define BUF_BYTES (128 * LDA * 4 + 2 * 128 * BNP * 4)   // 24576
#define AOFF(b)  ((b) * BUF_BYTES)
#define BHOFF(b) ((b) * BUF_BYTES + 128 * LDA * 4)
#define BLOFF(b) ((b) * BUF_BYTES + 128 * LDA * 4 + 128 * BNP * 4)
#define SMEM_TOT (3 * BUF_BYTES)                        // 73728

__global__ void __launch_bounds__(256, 2)
gemm_bf16_pipe(const float* __restrict__ A,
               const uint32_t* __restrict__ Bh0, const uint32_t* __restrict__ Bl0,
               const uint32_t* __restrict__ Bh1, const uint32_t* __restrict__ Bl1,
               float* __restrict__ C0, float* __restrict__ C1,
               const float* __restrict__ bias,
               const float* __restrict__ scale, const float* __restrict__ shift,
               int M, int K, int K2pad)
{
    extern __shared__ char smem[];
    const uint32_t sb = smem_u32(smem);

    const uint32_t* BhG = blockIdx.y ? Bh1 : Bh0;
    const uint32_t* BlG = blockIdx.y ? Bl1 : Bl0;
    float* C = blockIdx.y ? C1 : C0;
    const int mBase = blockIdx.x * 128;

    const int tid  = threadIdx.x;
    const int wid  = tid >> 5;
    const int lane = tid & 31;
    const int quad = lane >> 2;
    const int tq   = lane & 3;
    const int m0   = (wid & 3) * 32;
    const int n0   = (wid >> 2) * 64;
    const bool bn  = (scale != nullptr);

    const int ar0 = tid >> 2, ac0 = (tid & 3) * 4;
    const int ar1 = (tid + 256) >> 2, ac1 = ac0;
    const int bn_row = tid >> 1, bn_ch = (tid & 1) * 4;

    float acc[2][8][4];
    #pragma unroll
    for (int i = 0; i < 2; i++)
        #pragma unroll
        for (int j = 0; j < 8; j++)
            #pragma unroll
            for (int q = 0; q < 4; q++) acc[i][j][q] = 0.f;

    const int nT = (K + 15) / 16;

    auto issue_tile = [&](int t, int buf) {
        const int k0 = t * 16;
        {
            int gr = mBase + ar0;
            const float* src = A + (size_t)gr * K + k0 + ac0;
            int nb = (gr < M && (k0 + ac0) < K) ? 16 : 0;
            if (!nb) src = A;
            cp_async16(sb + AOFF(buf) + (ar0 * LDA + ac0) * 4, src, nb);
        }
        {
            int gr = mBase + ar1;
            const float* src = A + (size_t)gr * K + k0 + ac1;
            int nb = (gr < M && (k0 + ac1) < K) ? 16 : 0;
            if (!nb) src = A;
            cp_async16(sb + AOFF(buf) + (ar1 * LDA + ac1) * 4, src, nb);
        }
        {
            const uint32_t* srcH = BhG + (size_t)bn_row * K2pad + t * 8 + bn_ch;
            const uint32_t* srcL = BlG + (size_t)bn_row * K2pad + t * 8 + bn_ch;
            uint32_t d = (bn_row * BNP + bn_ch) * 4;
            cp_async16(sb + BHOFF(buf) + d, srcH, 16);
            cp_async16(sb + BLOFF(buf) + d, srcL, 16);
        }
        cp_commit();
    };

    issue_tile(0, 0);
    if (nT > 1) issue_tile(1, 1);

    for (int t = 0; t < nT; t++) {
        const int buf = t % 3;
        if (t + 2 < nT) {
            issue_tile(t + 2, (t + 2) % 3);
            cp_wait2();
        } else if (t + 1 < nT) {
            cp_wait1();
        } else {
            cp_wait0();
        }
        __syncthreads();

        const float* Ab = reinterpret_cast<const float*>(smem + AOFF(buf));
        const uint32_t* Bhb = reinterpret_cast<const uint32_t*>(smem + BHOFF(buf));
        const uint32_t* Blb = reinterpret_cast<const uint32_t*>(smem + BLOFF(buf));
        const int k0 = t * 16;

        float2 scA = make_float2(1.f, 1.f), shA = make_float2(0.f, 0.f);
        float2 scB = make_float2(1.f, 1.f), shB = make_float2(0.f, 0.f);
        if (bn) {
            scA = *reinterpret_cast<const float2*>(scale + k0 + 2 * tq);
            shA = *reinterpret_cast<const float2*>(shift + k0 + 2 * tq);
            scB = *reinterpret_cast<const float2*>(scale + k0 + 2 * tq + 8);
            shB = *reinterpret_cast<const float2*>(shift + k0 + 2 * tq + 8);
        }

        uint32_t ah[2][4], al[2][4];
        #pragma unroll
        for (int mi = 0; mi < 2; mi++) {
            int mr = m0 + mi * 16 + quad;
            float2 p0 = *reinterpret_cast<const float2*>(Ab + mr * LDA + 2 * tq);
            float2 p1 = *reinterpret_cast<const float2*>(Ab + (mr + 8) * LDA + 2 * tq);
            float2 p2 = *reinterpret_cast<const float2*>(Ab + mr * LDA + 2 * tq + 8);
            float2 p3 = *reinterpret_cast<const float2*>(Ab + (mr + 8) * LDA + 2 * tq + 8);
            if (bn) {
                p0.x = fmaxf(fmaf(p0.x, scA.x, shA.x), 0.f);
                p0.y = fmaxf(fmaf(p0.y, scA.y, shA.y), 0.f);
                p1.x = fmaxf(fmaf(p1.x, scA.x, shA.x), 0.f);
                p1.y = fmaxf(fmaf(p1.y, scA.y, shA.y), 0.f);
                p2.x = fmaxf(fmaf(p2.x, scB.x, shB.x), 0.f);
                p2.y = fmaxf(fmaf(p2.y, scB.y, shB.y), 0.f);
                p3.x = fmaxf(fmaf(p3.x, scB.x, shB.x), 0.f);
                p3.y = fmaxf(fmaf(p3.y, scB.y, shB.y), 0.f);
            }
            ah[mi][0] = pkbf(p0.x, p0.y);
            al[mi][0] = pkbf(p0.x - bflo(ah[mi][0]), p0.y - bfhi(ah[mi][0]));
            ah[mi][1] = pkbf(p1.x, p1.y);
            al[mi][1] = pkbf(p1.x - bflo(ah[mi][1]), p1.y - bfhi(ah[mi][1]));
            ah[mi][2] = pkbf(p2.x, p2.y);
            al[mi][2] = pkbf(p2.x - bflo(ah[mi][2]), p2.y - bfhi(ah[mi][2]));
            ah[mi][3] = pkbf(p3.x, p3.y);
            al[mi][3] = pkbf(p3.x - bflo(ah[mi][3]), p3.y - bfhi(ah[mi][3]));
        }

        #pragma unroll
        for (int ni = 0; ni < 8; ni++) {
            int nc = n0 + ni * 8 + quad;
            uint32_t bh0 = Bhb[nc * BNP + tq];
            uint32_t bh1 = Bhb[nc * BNP + tq + 4];
            uint32_t bl0 = Blb[nc * BNP + tq];
            uint32_t bl1 = Blb[nc * BNP + tq + 4];
            #pragma unroll
            for (int mi = 0; mi < 2; mi++) {
                mma_bf16(acc[mi][ni], ah[mi][0], ah[mi][1], ah[mi][2], ah[mi][3], bh0, bh1);
                mma_bf16(acc[mi][ni], ah[mi][0], ah[mi][1], ah[mi][2], ah[mi][3], bl0, bl1);
                mma_bf16(acc[mi][ni], al[mi][0], al[mi][1], al[mi][2], al[mi][3], bh0, bh1);
            }
        }
        __syncthreads();
    }

    const bool addb = (blockIdx.y != 0);
    #pragma unroll
    for (int mi = 0; mi < 2; mi++) {
        int r0 = mBase + m0 + mi * 16 + quad;
        #pragma unroll
        for (int ni = 0; ni < 8; ni++) {
            int col = n0 + ni * 8 + tq * 2;
            float2 bb = make_float2(0.f, 0.f);
            if (addb) bb = *reinterpret_cast<const float2*>(bias + col);
            if (r0 < M)
                *reinterpret_cast<float2*>(C + (size_t)r0 * HID + col) =
                    make_float2(acc[mi][ni][0] + bb.x, acc[mi][ni][1] + bb.y);
            if (r0 + 8 < M)
                *reinterpret_cast<float2*>(C + (size_t)(r0 + 8) * HID + col) =
                    make_float2(acc[mi][ni][2] + bb.x, acc[mi][ni][3] + bb.y);
        }
    }
}

// ---------------- zero kernel ----------------
__global__ void zero4_kernel(float4* __restrict__ p, int n4) {
    int i = blockIdx.x * blockDim.x + threadIdx.x;
    if (i < n4) p[i] = make_float4(0.f, 0.f, 0.f, 0.f);
}

// ---------------- fused dst-degree + src-histogram ----------------
__global__ void deg_hist_kernel(const int* __restrict__ ei, float* __restrict__ deg,
                                int* __restrict__ counts, int E) {
    int e = blockIdx.x * blockDim.x + threadIdx.x;
    if (e >= E) return;
    atomicAdd(&deg[ei[E + e]], 1.0f);
    atomicAdd(&counts[ei[e]], 1);
}

// ---------------- src-CSR build ----------------
__global__ void blocksum_kernel(const int* __restrict__ counts, int* __restrict__ bsum, int M) {
    __shared__ int sh[SBLK];
    int i = blockIdx.x * SBLK + threadIdx.x;
    sh[threadIdx.x] = (i < M) ? counts[i] : 0;
    __syncthreads();
    for (int off = SBLK / 2; off > 0; off >>= 1) {
        if (threadIdx.x < off) sh[threadIdx.x] += sh[threadIdx.x + off];
        __syncthreads();
    }
    if (threadIdx.x == 0) bsum[blockIdx.x] = sh[0];
}
// parallel exclusive scan of bsum[nb] (nb <= 256), one block of 256 threads
__global__ void bscan_kernel(int* __restrict__ bsum, int nb) {
    __shared__ int sh[256];
    int t = threadIdx.x;
    int v = (t < nb) ? bsum[t] : 0;
    sh[t] = v;
    __syncthreads();
    #pragma unroll
    for (int off = 1; off < 256; off <<= 1) {
        int u = (t >= off) ? sh[t - off] : 0;
        __syncthreads();
        sh[t] += u;
        __syncthreads();
    }
    if (t < nb) bsum[t] = sh[t] - v;   // exclusive
}
// local scan + rowptr/cursor fill + invdeg conversion (deg -> 1/max(deg,1))
__global__ void localscan_kernel(const int* __restrict__ counts, const int* __restrict__ boff,
                                 int* __restrict__ rowptr, int* __restrict__ cursor,
                                 float* __restrict__ deg, int M) {
    __shared__ int sh[SBLK];
    int i = blockIdx.x * SBLK + threadIdx.x;
    int c = (i < M) ? counts[i] : 0;
    sh[threadIdx.x] = c;
    __syncthreads();
    for (int off = 1; off < SBLK; off <<= 1) {
        int v = (threadIdx.x >= off) ? sh[threadIdx.x - off] : 0;
        __syncthreads();
        sh[threadIdx.x] += v;
        __syncthreads();
    }
    int excl = boff[blockIdx.x] + sh[threadIdx.x] - c;
    if (i < M) {
        rowptr[i] = excl;
        cursor[i] = excl;
        deg[i] = 1.0f / fmaxf(deg[i], 1.0f);
    }
    if (i == M - 1) rowptr[M] = excl + c;
}
__global__ void fill_kernel(const int* __restrict__ ei, int* __restrict__ cursor,
                            int* __restrict__ csrdst, int E) {
    int e = blockIdx.x * blockDim.x + threadIdx.x;
    if (e >= E) return;
    int s = ei[e];
    int pos = atomicAdd(&cursor[s], 1);
    csrdst[pos] = ei[E + e];
}

// ---------------- warp-per-src scatter ----------------
__global__ void scatter_src_kernel(const float* __restrict__ xl,
                                   const int* __restrict__ rowptr,
                                   const int* __restrict__ csrdst,
                                   const float* __restrict__ invdeg,
                                   float* __restrict__ h, int M)
{
    int warp = (blockIdx.x * blockDim.x + threadIdx.x) >> 5;
    int lane = threadIdx.x & 31;
    if (warp >= M) return;
    int rs = rowptr[warp], re = rowptr[warp + 1];
    if (rs == re) return;
    float4 v = reinterpret_cast<const float4*>(xl)[warp * 32 + lane];
    for (int e = rs; e < re; e++) {
        int d = csrdst[e];
        float inv = invdeg[d];
        float4 w = make_float4(v.x * inv, v.y * inv, v.z * inv, v.w * inv);
        red_add_v4(h + (size_t)d * HID + lane * 4, w);
    }
}

// ---------------- BN stats over h ----------------
#define ROWS_PB 64
__global__ void stats_kernel(const float* __restrict__ h,
                             float* __restrict__ colsum,
                             float* __restrict__ colsumsq, int M)
{
    int col = threadIdx.x;
    int r0 = blockIdx.x * ROWS_PB;
    int r1 = min(r0 + ROWS_PB, M);
    float s = 0.f, s2 = 0.f;
    for (int r = r0; r < r1; r++) {
        float v = h[(size_t)r * HID + col];
        s += v; s2 += v * v;
    }
    atomicAdd(&colsum[col], s);
    atomicAdd(&colsumsq[col], s2);
}

// ---------------- BN finalize ----------------
__global__ void bn_finalize(float* __restrict__ colsum,
                            float* __restrict__ colsumsq,
                            const float* __restrict__ gamma,
                            const float* __restrict__ beta,
                            float* __restrict__ scale,
                            float* __restrict__ shift, int M)
{
    int c = threadIdx.x;
    float invM = 1.0f / (float)M;
    float mu = colsum[c] * invM;
    float var = colsumsq[c] * invM - mu * mu;
    float rs = rsqrtf(var + 1e-5f);
    float sc = rs * gamma[c];
    scale[c] = sc;
    shift[c] = beta[c] - mu * sc;
    colsum[c] = 0.f;
    colsumsq[c] = 0.f;
}

// ---------------- pool with fused BN+relu ----------------
__global__ void pool_bn_kernel(const float* __restrict__ h,
                               const int* __restrict__ batch,
                               const float* __restrict__ scale,
                               const float* __restrict__ shift,
                               float* __restrict__ pooled,
                               float* __restrict__ cnt, int M)
{
    int warp = (blockIdx.x * blockDim.x + threadIdx.x) >> 5;
    int lane = threadIdx.x & 31;
    if (warp >= M) return;
    int g = batch[warp];
    float4 v = reinterpret_cast<const float4*>(h)[warp * 32 + lane];
    float4 sc = reinterpret_cast<const float4*>(scale)[lane];
    float4 sh = reinterpret_cast<const float4*>(shift)[lane];
    v.x = fmaxf(fmaf(v.x, sc.x, sh.x), 0.f);
    v.y = fmaxf(fmaf(v.y, sc.y, sh.y), 0.f);
    v.z = fmaxf(fmaf(v.z, sc.z, sh.z), 0.f);
    v.w = fmaxf(fmaf(v.w, sc.w, sh.w), 0.f);
    red_add_v4(pooled + (long long)g * HID + lane * 4, v);
    if (lane == 0) atomicAdd(&cnt[g], 1.0f);
}

// ---------------- head ----------------
__global__ void head_kernel(const float* __restrict__ pooled,
                            const float* __restrict__ cnt,
                            const float* __restrict__ Wc,
                            const float* __restrict__ bc,
                            float* __restrict__ out, int mode)
{
    int g = threadIdx.x;
    float c = fmaxf(cnt[g], 1.f);
    float inv = 1.0f / c;
    float a0 = bc[0], a1 = bc[1];
    float* hg_out = (mode == 0) ? (out + 2 * NGRAPH) : out;
    for (int k = 0; k < HID; k++) {
        float v = pooled[g * HID + k] * inv;
        if (mode != 1) hg_out[g * HID + k] = v;
        a0 = fmaf(v, Wc[k * 2 + 0], a0);
        a1 = fmaf(v, Wc[k * 2 + 1], a1);
    }
    if (mode != 2) {
        out[g * 2 + 0] = a0;
        out[g * 2 + 1] = a1;
    }
}

// ---------------- launcher ----------------
extern "C" void kernel_launch(void* const* d_in, const int* in_sizes, int n_in,
                              void* d_out, int out_size)
{
    const float* x     = (const float*)d_in[0];
    const int*   ei    = (const int*)d_in[1];
    const int*   batch = (const int*)d_in[2];

    const float* Wl[3] = { (const float*)d_in[3],  (const float*)d_in[8],  (const float*)d_in[13] };
    const float* Wr[3] = { (const float*)d_in[4],  (const float*)d_in[9],  (const float*)d_in[14] };
    const float* bi[3] = { (const float*)d_in[5],  (const float*)d_in[10], (const float*)d_in[15] };
    const float* ga[3] = { (const float*)d_in[6],  (const float*)d_in[11], (const float*)d_in[16] };
    const float* be[3] = { (const float*)d_in[7],  (const float*)d_in[12], (const float*)d_in[17] };
    const float* Wc = (const float*)d_in[18];
    const float* bc = (const float*)d_in[19];

    float* base = nullptr;
    cudaGetSymbolAddress((void**)&base, g_scratch);

    float* xl       = base;
    float* hA       = xl + NF;
    float* hB       = hA + NF;
    float* colsum   = hB + NF;
    float* colsumsq = colsum + HID;
    float* pooled   = colsumsq + HID;
    float* cnt      = pooled + NGRAPH * HID;
    float* scale    = cnt + NGRAPH;
    float* shift    = scale + HID;
    float* invdeg   = shift + HID;
    uint32_t* Wh    = (uint32_t*)(invdeg + M_NODES);
    uint32_t* Wlo   = Wh + WPK_TOT;
    int* rowptr     = (int*)(Wlo + WPK_TOT);
    int* cursor     = rowptr + M_NODES + 4;
    int* csrdst     = cursor + M_NODES;
    int* bsum       = csrdst + E_EDGES;

    const int woff[3][2] = { {0, 19456}, {38912, 47104}, {55296, 63488} };
    const int K2p[3] = { 152, 64, 64 };

    const int M = M_NODES, E = E_EDGES;
    float* out = (float*)d_out;

    int mode = 0;
    if (out_size < 16640) mode = (out_size >= 16384) ? 2 : 1;

    cudaFuncSetAttribute(gemm_bf16_pipe,
                         cudaFuncAttributeMaxDynamicSharedMemorySize, SMEM_TOT);

    // ---- setup ----
    {
        int z4 = (2 * HID + NGRAPH * HID + NGRAPH) / 4;
        zero4_kernel<<<(z4 + 255) / 256, 256>>>((float4*)colsum, z4);
        zero4_kernel<<<(M / 4 + 255) / 256, 256>>>((float4*)invdeg, M / 4);
        zero4_kernel<<<(M / 4 + 255) / 256, 256>>>((float4*)cursor, M / 4);
        deg_hist_kernel<<<(E + 255) / 256, 256>>>(ei, invdeg, cursor, E);
        blocksum_kernel<<<NBLK, SBLK>>>(cursor, bsum, M);
        bscan_kernel<<<1, 256>>>(bsum, NBLK);
        localscan_kernel<<<NBLK, SBLK>>>(cursor, bsum, rowptr, cursor, invdeg, M);
        fill_kernel<<<(E + 255) / 256, 256>>>(ei, cursor, csrdst, E);
        split_w_all<<<(WPK_TOT + 255) / 256, 256>>>(Wl[0], Wr[0], Wl[1], Wr[1], Wl[2], Wr[2],
                                                    Wh, Wlo);
    }

    float* hout[3] = { hA, hB, hA };
    const float* hin[3] = { x, hA, hB };

    int K = IN_CH;
    for (int l = 0; l < 3; l++) {
        const float* sc = (l == 0) ? nullptr : scale;
        const float* sh = (l == 0) ? nullptr : shift;

        dim3 grid((M + 127) / 128, 2);
        gemm_bf16_pipe<<<grid, 256, SMEM_TOT>>>(hin[l],
                                                Wh + woff[l][0], Wlo + woff[l][0],
                                                Wh + woff[l][1], Wlo + woff[l][1],
                                                xl, hout[l], bi[l], sc, sh, M, K, K2p[l]);

        scatter_src_kernel<<<(M * 32 + 255) / 256, 256>>>(xl, rowptr, csrdst, invdeg,
                                                          hout[l], M);

        stats_kernel<<<(M + ROWS_PB - 1) / ROWS_PB, HID>>>(hout[l], colsum, colsumsq, M);
        bn_finalize<<<1, HID>>>(colsum, colsumsq, ga[l], be[l], scale, shift, M);

        K = HID;
    }

    pool_bn_kernel<<<(M * 32 + 255) / 256, 256>>>(hA, batch, scale, shift, pooled, cnt, M);
    head_kernel<<<1, NGRAPH>>>(pooled, cnt, Wc, bc, out, mode);
}

// round 15
// speedup vs baseline: 1.2301x; 1.2063x over previous
#include <cuda_runtime.h>
#include <cstdint>

// ---------------- problem constants ----------------
#define M_NODES 50000
#define E_EDGES 600000
#define IN_CH   300
#define HID     128
#define NGRAPH  128
#define NF      (M_NODES * HID)   // 6,400,000
#define WPK_TOT 71680
#define SBLK    256
#define NBLK    ((M_NODES + SBLK - 1) / SBLK)   // 196

// ---------------- scratch (static device memory; no allocs) ----------------
__device__ __align__(16) float g_scratch[3 * NF + 256 + 16384 + 128 + 256 + M_NODES
                                         + 2 * WPK_TOT + 2 * M_NODES + E_EDGES + NBLK + 64];

// ---------------- helpers ----------------
__device__ __forceinline__ void red_add_v4(float* addr, float4 v) {
    asm volatile("red.global.add.v4.f32 [%0], {%1, %2, %3, %4};"
                 :: "l"(addr), "f"(v.x), "f"(v.y), "f"(v.z), "f"(v.w) : "memory");
}
__device__ __forceinline__ uint32_t pkbf(float lo, float hi) {
    uint32_t r;
    asm("cvt.rn.bf16x2.f32 %0, %1, %2;" : "=r"(r) : "f"(hi), "f"(lo));
    return r;
}
__device__ __forceinline__ float bflo(uint32_t p) { return __uint_as_float(p << 16); }
__device__ __forceinline__ float bfhi(uint32_t p) { return __uint_as_float(p & 0xFFFF0000u); }

__device__ __forceinline__ void mma_bf16(float c[4],
                                         uint32_t a0, uint32_t a1, uint32_t a2, uint32_t a3,
                                         uint32_t b0, uint32_t b1) {
    asm volatile(
        "mma.sync.aligned.m16n8k16.row.col.f32.bf16.bf16.f32 "
        "{%0,%1,%2,%3}, {%4,%5,%6,%7}, {%8,%9}, {%0,%1,%2,%3};"
        : "+f"(c[0]), "+f"(c[1]), "+f"(c[2]), "+f"(c[3])
        : "r"(a0), "r"(a1), "r"(a2), "r"(a3), "r"(b0), "r"(b1));
}
__device__ __forceinline__ uint32_t smem_u32(const void* p) {
    uint32_t a;
    asm("{ .reg .u64 t; cvta.to.shared.u64 t, %1; cvt.u32.u64 %0, t; }" : "=r"(a) : "l"(p));
    return a;
}
__device__ __forceinline__ void cp_async16(uint32_t dst, const void* src, int nb) {
    asm volatile("cp.async.cg.shared.global [%0], [%1], 16, %2;"
                 :: "r"(dst), "l"(src), "r"(nb) : "memory");
}
__device__ __forceinline__ void cp_commit() { asm volatile("cp.async.commit_group;" ::: "memory"); }
__device__ __forceinline__ void cp_wait2()  { asm volatile("cp.async.wait_group 2;" ::: "memory"); }
__device__ __forceinline__ void cp_wait1()  { asm volatile("cp.async.wait_group 1;" ::: "memory"); }
__device__ __forceinline__ void cp_wait0()  { asm volatile("cp.async.wait_group 0;" ::: "memory"); }

// ---------------- split ALL weights once ----------------
__global__ void split_w_all(const float* __restrict__ W0, const float* __restrict__ W1,
                            const float* __restrict__ W2, const float* __restrict__ W3,
                            const float* __restrict__ W4, const float* __restrict__ W5,
                            uint32_t* __restrict__ Wh, uint32_t* __restrict__ Wl)
{
    int i = blockIdx.x * blockDim.x + threadIdx.x;
    if (i >= WPK_TOT) return;
    const float* W;
    int base, K, K2pad;
    if      (i < 19456) { W = W0; base = 0;     K = 300; K2pad = 152; }
    else if (i < 38912) { W = W1; base = 19456; K = 300; K2pad = 152; }
    else if (i < 47104) { W = W2; base = 38912; K = 128; K2pad = 64; }
    else if (i < 55296) { W = W3; base = 47104; K = 128; K2pad = 64; }
    else if (i < 63488) { W = W4; base = 55296; K = 128; K2pad = 64; }
    else                { W = W5; base = 63488; K = 128; K2pad = 64; }
    int j = i - base;
    int n = j / K2pad, k2 = j % K2pad;
    float w0 = (2 * k2     < K) ? W[(size_t)(2 * k2)     * HID + n] : 0.f;
    float w1 = (2 * k2 + 1 < K) ? W[(size_t)(2 * k2 + 1) * HID + n] : 0.f;
    uint32_t hh = pkbf(w0, w1);
    Wh[i] = hh;
    Wl[i] = pkbf(w0 - bflo(hh), w1 - bfhi(hh));
}

// ---------------- 3-stage pipelined BF16x3 tensor GEMM (unchanged, proven) ----------------
#define LDA   24
#define BNP   12
#define BUF_BYTES (128 * LDA * 4 + 2 * 128 * BNP * 4)   // 24576
#define AOFF(b)  ((b) * BUF_BYTES)
#define BHOFF(b) ((b) * BUF_BYTES + 128 * LDA * 4)
#define BLOFF(b) ((b) * BUF_BYTES + 128 * LDA * 4 + 128 * BNP * 4)
#define SMEM_TOT (3 * BUF_BYTES)                        // 73728

__global__ void __launch_bounds__(256, 2)
gemm_bf16_pipe(const float* __restrict__ A,
               const uint32_t* __restrict__ Bh0, const uint32_t* __restrict__ Bl0,
               const uint32_t* __restrict__ Bh1, const uint32_t* __restrict__ Bl1,
               float* __restrict__ C0, float* __restrict__ C1,
               const float* __restrict__ bias,
               const float* __restrict__ scale, const float* __restrict__ shift,
               int M, int K, int K2pad)
{
    extern __shared__ char smem[];
    const uint32_t sb = smem_u32(smem);

    const uint32_t* BhG = blockIdx.y ? Bh1 : Bh0;
    const uint32_t* BlG = blockIdx.y ? Bl1 : Bl0;
    float* C = blockIdx.y ? C1 : C0;
    const int mBase = blockIdx.x * 128;

    const int tid  = threadIdx.x;
    const int wid  = tid >> 5;
    const int lane = tid & 31;
    const int quad = lane >> 2;
    const int tq   = lane & 3;
    const int m0   = (wid & 3) * 32;
    const int n0   = (wid >> 2) * 64;
    const bool bn  = (scale != nullptr);

    const int ar0 = tid >> 2, ac0 = (tid & 3) * 4;
    const int ar1 = (tid + 256) >> 2, ac1 = ac0;
    const int bn_row = tid >> 1, bn_ch = (tid & 1) * 4;

    float acc[2][8][4];
    #pragma unroll
    for (int i = 0; i < 2; i++)
        #pragma unroll
        for (int j = 0; j < 8; j++)
            #pragma unroll
            for (int q = 0; q < 4; q++) acc[i][j][q] = 0.f;

    const int nT = (K + 15) / 16;

    auto issue_tile = [&](int t, int buf) {
        const int k0 = t * 16;
        {
            int gr = mBase + ar0;
            const float* src = A + (size_t)gr * K + k0 + ac0;
            int nb = (gr < M && (k0 + ac0) < K) ? 16 : 0;
            if (!nb) src = A;
            cp_async16(sb + AOFF(buf) + (ar0 * LDA + ac0) * 4, src, nb);
        }
        {
            int gr = mBase + ar1;
            const float* src = A + (size_t)gr * K + k0 + ac1;
            int nb = (gr < M && (k0 + ac1) < K) ? 16 : 0;
            if (!nb) src = A;
            cp_async16(sb + AOFF(buf) + (ar1 * LDA + ac1) * 4, src, nb);
        }
        {
            const uint32_t* srcH = BhG + (size_t)bn_row * K2pad + t * 8 + bn_ch;
            const uint32_t* srcL = BlG + (size_t)bn_row * K2pad + t * 8 + bn_ch;
            uint32_t d = (bn_row * BNP + bn_ch) * 4;
            cp_async16(sb + BHOFF(buf) + d, srcH, 16);
            cp_async16(sb + BLOFF(buf) + d, srcL, 16);
        }
        cp_commit();
    };

    issue_tile(0, 0);
    if (nT > 1) issue_tile(1, 1);

    for (int t = 0; t < nT; t++) {
        const int buf = t % 3;
        if (t + 2 < nT) {
            issue_tile(t + 2, (t + 2) % 3);
            cp_wait2();
        } else if (t + 1 < nT) {
            cp_wait1();
        } else {
            cp_wait0();
        }
        __syncthreads();

        const float* Ab = reinterpret_cast<const float*>(smem + AOFF(buf));
        const uint32_t* Bhb = reinterpret_cast<const uint32_t*>(smem + BHOFF(buf));
        const uint32_t* Blb = reinterpret_cast<const uint32_t*>(smem + BLOFF(buf));
        const int k0 = t * 16;

        float2 scA = make_float2(1.f, 1.f), shA = make_float2(0.f, 0.f);
        float2 scB = make_float2(1.f, 1.f), shB = make_float2(0.f, 0.f);
        if (bn) {
            scA = *reinterpret_cast<const float2*>(scale + k0 + 2 * tq);
            shA = *reinterpret_cast<const float2*>(shift + k0 + 2 * tq);
            scB = *reinterpret_cast<const float2*>(scale + k0 + 2 * tq + 8);
            shB = *reinterpret_cast<const float2*>(shift + k0 + 2 * tq + 8);
        }

        uint32_t ah[2][4], al[2][4];
        #pragma unroll
        for (int mi = 0; mi < 2; mi++) {
            int mr = m0 + mi * 16 + quad;
            float2 p0 = *reinterpret_cast<const float2*>(Ab + mr * LDA + 2 * tq);
            float2 p1 = *reinterpret_cast<const float2*>(Ab + (mr + 8) * LDA + 2 * tq);
            float2 p2 = *reinterpret_cast<const float2*>(Ab + mr * LDA + 2 * tq + 8);
            float2 p3 = *reinterpret_cast<const float2*>(Ab + (mr + 8) * LDA + 2 * tq + 8);
            if (bn) {
                p0.x = fmaxf(fmaf(p0.x, scA.x, shA.x), 0.f);
                p0.y = fmaxf(fmaf(p0.y, scA.y, shA.y), 0.f);
                p1.x = fmaxf(fmaf(p1.x, scA.x, shA.x), 0.f);
                p1.y = fmaxf(fmaf(p1.y, scA.y, shA.y), 0.f);
                p2.x = fmaxf(fmaf(p2.x, scB.x, shB.x), 0.f);
                p2.y = fmaxf(fmaf(p2.y, scB.y, shB.y), 0.f);
                p3.x = fmaxf(fmaf(p3.x, scB.x, shB.x), 0.f);
                p3.y = fmaxf(fmaf(p3.y, scB.y, shB.y), 0.f);
            }
            ah[mi][0] = pkbf(p0.x, p0.y);
            al[mi][0] = pkbf(p0.x - bflo(ah[mi][0]), p0.y - bfhi(ah[mi][0]));
            ah[mi][1] = pkbf(p1.x, p1.y);
            al[mi][1] = pkbf(p1.x - bflo(ah[mi][1]), p1.y - bfhi(ah[mi][1]));
            ah[mi][2] = pkbf(p2.x, p2.y);
            al[mi][2] = pkbf(p2.x - bflo(ah[mi][2]), p2.y - bfhi(ah[mi][2]));
            ah[mi][3] = pkbf(p3.x, p3.y);
            al[mi][3] = pkbf(p3.x - bflo(ah[mi][3]), p3.y - bfhi(ah[mi][3]));
        }

        #pragma unroll
        for (int ni = 0; ni < 8; ni++) {
            int nc = n0 + ni * 8 + quad;
            uint32_t bh0 = Bhb[nc * BNP + tq];
            uint32_t bh1 = Bhb[nc * BNP + tq + 4];
            uint32_t bl0 = Blb[nc * BNP + tq];
            uint32_t bl1 = Blb[nc * BNP + tq + 4];
            #pragma unroll
            for (int mi = 0; mi < 2; mi++) {
                mma_bf16(acc[mi][ni], ah[mi][0], ah[mi][1], ah[mi][2], ah[mi][3], bh0, bh1);
                mma_bf16(acc[mi][ni], ah[mi][0], ah[mi][1], ah[mi][2], ah[mi][3], bl0, bl1);
                mma_bf16(acc[mi][ni], al[mi][0], al[mi][1], al[mi][2], al[mi][3], bh0, bh1);
            }
        }
        __syncthreads();
    }

    const bool addb = (blockIdx.y != 0);
    #pragma unroll
    for (int mi = 0; mi < 2; mi++) {
        int r0 = mBase + m0 + mi * 16 + quad;
        #pragma unroll
        for (int ni = 0; ni < 8; ni++) {
            int col = n0 + ni * 8 + tq * 2;
            float2 bb = make_float2(0.f, 0.f);
            if (addb) bb = *reinterpret_cast<const float2*>(bias + col);
            if (r0 < M)
                *reinterpret_cast<float2*>(C + (size_t)r0 * HID + col) =
                    make_float2(acc[mi][ni][0] + bb.x, acc[mi][ni][1] + bb.y);
            if (r0 + 8 < M)
                *reinterpret_cast<float2*>(C + (size_t)(r0 + 8) * HID + col) =
                    make_float2(acc[mi][ni][2] + bb.x, acc[mi][ni][3] + bb.y);
        }
    }
}

// ---------------- zero kernel ----------------
__global__ void zero4_kernel(float4* __restrict__ p, int n4) {
    int i = blockIdx.x * blockDim.x + threadIdx.x;
    if (i < n4) p[i] = make_float4(0.f, 0.f, 0.f, 0.f);
}

// ---------------- dst histogram (int counts) ----------------
__global__ void dst_hist_kernel(const int* __restrict__ ei, int* __restrict__ counts, int E) {
    int e = blockIdx.x * blockDim.x + threadIdx.x;
    if (e < E) atomicAdd(&counts[ei[E + e]], 1);
}

// ---------------- dst-CSR build ----------------
__global__ void blocksum_kernel(const int* __restrict__ counts, int* __restrict__ bsum, int M) {
    __shared__ int sh[SBLK];
    int i = blockIdx.x * SBLK + threadIdx.x;
    sh[threadIdx.x] = (i < M) ? counts[i] : 0;
    __syncthreads();
    for (int off = SBLK / 2; off > 0; off >>= 1) {
        if (threadIdx.x < off) sh[threadIdx.x] += sh[threadIdx.x + off];
        __syncthreads();
    }
    if (threadIdx.x == 0) bsum[blockIdx.x] = sh[0];
}
__global__ void bscan_kernel(int* __restrict__ bsum, int nb) {
    __shared__ int sh[256];
    int t = threadIdx.x;
    int v = (t < nb) ? bsum[t] : 0;
    sh[t] = v;
    __syncthreads();
    #pragma unroll
    for (int off = 1; off < 256; off <<= 1) {
        int u = (t >= off) ? sh[t - off] : 0;
        __syncthreads();
        sh[t] += u;
        __syncthreads();
    }
    if (t < nb) bsum[t] = sh[t] - v;   // exclusive
}
// local scan + rowptr/cursor fill + invdeg from dst counts
__global__ void localscan_kernel(const int* __restrict__ counts, const int* __restrict__ boff,
                                 int* __restrict__ rowptr, int* __restrict__ cursor,
                                 float* __restrict__ invdeg, int M) {
    __shared__ int sh[SBLK];
    int i = blockIdx.x * SBLK + threadIdx.x;
    int c = (i < M) ? counts[i] : 0;
    sh[threadIdx.x] = c;
    __syncthreads();
    for (int off = 1; off < SBLK; off <<= 1) {
        int v = (threadIdx.x >= off) ? sh[threadIdx.x - off] : 0;
        __syncthreads();
        sh[threadIdx.x] += v;
        __syncthreads();
    }
    int excl = boff[blockIdx.x] + sh[threadIdx.x] - c;
    if (i < M) {
        rowptr[i] = excl;
        cursor[i] = excl;
        invdeg[i] = 1.0f / (float)max(c, 1);
    }
    if (i == M - 1) rowptr[M] = excl + c;
}
__global__ void fill_kernel(const int* __restrict__ ei, int* __restrict__ cursor,
                            int* __restrict__ csrsrc, int E) {
    int e = blockIdx.x * blockDim.x + threadIdx.x;
    if (e >= E) return;
    int d = ei[E + e];
    int pos = atomicAdd(&cursor[d], 1);
    csrsrc[pos] = ei[e];
}

// ---------------- warp-per-dst GATHER: h[d] += mean of xl[src] (no atomics) ----------------
__global__ void gather_dst_kernel(const float* __restrict__ xl,
                                  const int* __restrict__ rowptr,
                                  const int* __restrict__ csrsrc,
                                  const float* __restrict__ invdeg,
                                  float* __restrict__ h, int M)
{
    int warp = (blockIdx.x * blockDim.x + threadIdx.x) >> 5;
    int lane = threadIdx.x & 31;
    if (warp >= M) return;
    int rs = rowptr[warp], re = rowptr[warp + 1];
    if (rs == re) return;

    const float4* x4 = reinterpret_cast<const float4*>(xl);
    float4 a0 = make_float4(0.f, 0.f, 0.f, 0.f);
    float4 a1 = a0, a2 = a0, a3 = a0;

    int e = rs;
    for (; e + 4 <= re; e += 4) {
        int s0 = csrsrc[e],     s1 = csrsrc[e + 1];
        int s2 = csrsrc[e + 2], s3 = csrsrc[e + 3];
        float4 v0 = x4[s0 * 32 + lane];
        float4 v1 = x4[s1 * 32 + lane];
        float4 v2 = x4[s2 * 32 + lane];
        float4 v3 = x4[s3 * 32 + lane];
        a0.x += v0.x; a0.y += v0.y; a0.z += v0.z; a0.w += v0.w;
        a1.x += v1.x; a1.y += v1.y; a1.z += v1.z; a1.w += v1.w;
        a2.x += v2.x; a2.y += v2.y; a2.z += v2.z; a2.w += v2.w;
        a3.x += v3.x; a3.y += v3.y; a3.z += v3.z; a3.w += v3.w;
    }
    for (; e < re; e++) {
        float4 v = x4[csrsrc[e] * 32 + lane];
        a0.x += v.x; a0.y += v.y; a0.z += v.z; a0.w += v.w;
    }
    float inv = invdeg[warp];
    float4 s;
    s.x = ((a0.x + a1.x) + (a2.x + a3.x)) * inv;
    s.y = ((a0.y + a1.y) + (a2.y + a3.y)) * inv;
    s.z = ((a0.z + a1.z) + (a2.z + a3.z)) * inv;
    s.w = ((a0.w + a1.w) + (a2.w + a3.w)) * inv;

    float4* hp = reinterpret_cast<float4*>(h) + (size_t)warp * 32 + lane;
    float4 cur = *hp;
    cur.x += s.x; cur.y += s.y; cur.z += s.z; cur.w += s.w;
    *hp = cur;
}

// ---------------- BN stats over h ----------------
#define ROWS_PB 64
__global__ void stats_kernel(const float* __restrict__ h,
                             float* __restrict__ colsum,
                             float* __restrict__ colsumsq, int M)
{
    int col = threadIdx.x;
    int r0 = blockIdx.x * ROWS_PB;
    int r1 = min(r0 + ROWS_PB, M);
    float s = 0.f, s2 = 0.f;
    for (int r = r0; r < r1; r++) {
        float v = h[(size_t)r * HID + col];
        s += v; s2 += v * v;
    }
    atomicAdd(&colsum[col], s);
    atomicAdd(&colsumsq[col], s2);
}

// ---------------- BN finalize ----------------
__global__ void bn_finalize(float* __restrict__ colsum,
                            float* __restrict__ colsumsq,
                            const float* __restrict__ gamma,
                            const float* __restrict__ beta,
                            float* __restrict__ scale,
                            float* __restrict__ shift, int M)
{
    int c = threadIdx.x;
    float invM = 1.0f / (float)M;
    float mu = colsum[c] * invM;
    float var = colsumsq[c] * invM - mu * mu;
    float rs = rsqrtf(var + 1e-5f);
    float sc = rs * gamma[c];
    scale[c] = sc;
    shift[c] = beta[c] - mu * sc;
    colsum[c] = 0.f;
    colsumsq[c] = 0.f;
}

// ---------------- pool with fused BN+relu ----------------
__global__ void pool_bn_kernel(const float* __restrict__ h,
                               const int* __restrict__ batch,
                               const float* __restrict__ scale,
                               const float* __restrict__ shift,
                               float* __restrict__ pooled,
                               float* __restrict__ cnt, int M)
{
    int warp = (blockIdx.x * blockDim.x + threadIdx.x) >> 5;
    int lane = threadIdx.x & 31;
    if (warp >= M) return;
    int g = batch[warp];
    float4 v = reinterpret_cast<const float4*>(h)[warp * 32 + lane];
    float4 sc = reinterpret_cast<const float4*>(scale)[lane];
    float4 sh = reinterpret_cast<const float4*>(shift)[lane];
    v.x = fmaxf(fmaf(v.x, sc.x, sh.x), 0.f);
    v.y = fmaxf(fmaf(v.y, sc.y, sh.y), 0.f);
    v.z = fmaxf(fmaf(v.z, sc.z, sh.z), 0.f);
    v.w = fmaxf(fmaf(v.w, sc.w, sh.w), 0.f);
    red_add_v4(pooled + (long long)g * HID + lane * 4, v);
    if (lane == 0) atomicAdd(&cnt[g], 1.0f);
}

// ---------------- head ----------------
__global__ void head_kernel(const float* __restrict__ pooled,
                            const float* __restrict__ cnt,
                            const float* __restrict__ Wc,
                            const float* __restrict__ bc,
                            float* __restrict__ out, int mode)
{
    int g = threadIdx.x;
    float c = fmaxf(cnt[g], 1.f);
    float inv = 1.0f / c;
    float a0 = bc[0], a1 = bc[1];
    float* hg_out = (mode == 0) ? (out + 2 * NGRAPH) : out;
    for (int k = 0; k < HID; k++) {
        float v = pooled[g * HID + k] * inv;
        if (mode != 1) hg_out[g * HID + k] = v;
        a0 = fmaf(v, Wc[k * 2 + 0], a0);
        a1 = fmaf(v, Wc[k * 2 + 1], a1);
    }
    if (mode != 2) {
        out[g * 2 + 0] = a0;
        out[g * 2 + 1] = a1;
    }
}

// ---------------- launcher ----------------
extern "C" void kernel_launch(void* const* d_in, const int* in_sizes, int n_in,
                              void* d_out, int out_size)
{
    const float* x     = (const float*)d_in[0];
    const int*   ei    = (const int*)d_in[1];
    const int*   batch = (const int*)d_in[2];

    const float* Wl[3] = { (const float*)d_in[3],  (const float*)d_in[8],  (const float*)d_in[13] };
    const float* Wr[3] = { (const float*)d_in[4],  (const float*)d_in[9],  (const float*)d_in[14] };
    const float* bi[3] = { (const float*)d_in[5],  (const float*)d_in[10], (const float*)d_in[15] };
    const float* ga[3] = { (const float*)d_in[6],  (const float*)d_in[11], (const float*)d_in[16] };
    const float* be[3] = { (const float*)d_in[7],  (const float*)d_in[12], (const float*)d_in[17] };
    const float* Wc = (const float*)d_in[18];
    const float* bc = (const float*)d_in[19];

    float* base = nullptr;
    cudaGetSymbolAddress((void**)&base, g_scratch);

    float* xl       = base;
    float* hA       = xl + NF;
    float* hB       = hA + NF;
    float* colsum   = hB + NF;
    float* colsumsq = colsum + HID;
    float* pooled   = colsumsq + HID;
    float* cnt      = pooled + NGRAPH * HID;
    float* scale    = cnt + NGRAPH;
    float* shift    = scale + HID;
    float* invdeg   = shift + HID;
    uint32_t* Wh    = (uint32_t*)(invdeg + M_NODES);
    uint32_t* Wlo   = Wh + WPK_TOT;
    int* rowptr     = (int*)(Wlo + WPK_TOT);
    int* cursor     = rowptr + M_NODES + 4;
    int* csrsrc     = cursor + M_NODES;
    int* bsum       = csrsrc + E_EDGES;

    const int woff[3][2] = { {0, 19456}, {38912, 47104}, {55296, 63488} };
    const int K2p[3] = { 152, 64, 64 };

    const int M = M_NODES, E = E_EDGES;
    float* out = (float*)d_out;

    int mode = 0;
    if (out_size < 16640) mode = (out_size >= 16384) ? 2 : 1;

    cudaFuncSetAttribute(gemm_bf16_pipe,
                         cudaFuncAttributeMaxDynamicSharedMemorySize, SMEM_TOT);

    // ---- setup: dst-CSR + invdeg + packed weights ----
    {
        int z4 = (2 * HID + NGRAPH * HID + NGRAPH) / 4;
        zero4_kernel<<<(z4 + 255) / 256, 256>>>((float4*)colsum, z4);
        zero4_kernel<<<(M / 4 + 255) / 256, 256>>>((float4*)cursor, M / 4);
        dst_hist_kernel<<<(E + 255) / 256, 256>>>(ei, cursor, E);
        blocksum_kernel<<<NBLK, SBLK>>>(cursor, bsum, M);
        bscan_kernel<<<1, 256>>>(bsum, NBLK);
        localscan_kernel<<<NBLK, SBLK>>>(cursor, bsum, rowptr, cursor, invdeg, M);
        fill_kernel<<<(E + 255) / 256, 256>>>(ei, cursor, csrsrc, E);
        split_w_all<<<(WPK_TOT + 255) / 256, 256>>>(Wl[0], Wr[0], Wl[1], Wr[1], Wl[2], Wr[2],
                                                    Wh, Wlo);
    }

    float* hout[3] = { hA, hB, hA };
    const float* hin[3] = { x, hA, hB };

    int K = IN_CH;
    for (int l = 0; l < 3; l++) {
        const float* sc = (l == 0) ? nullptr : scale;
        const float* sh = (l == 0) ? nullptr : shift;

        dim3 grid((M + 127) / 128, 2);
        gemm_bf16_pipe<<<grid, 256, SMEM_TOT>>>(hin[l],
                                                Wh + woff[l][0], Wlo + woff[l][0],
                                                Wh + woff[l][1], Wlo + woff[l][1],
                                                xl, hout[l], bi[l], sc, sh, M, K, K2p[l]);

        gather_dst_kernel<<<(M * 32 + 255) / 256, 256>>>(xl, rowptr, csrsrc, invdeg,
                                                         hout[l], M);

        stats_kernel<<<(M + ROWS_PB - 1) / ROWS_PB, HID>>>(hout[l], colsum, colsumsq, M);
        bn_finalize<<<1, HID>>>(colsum, colsumsq, ga[l], be[l], scale, shift, M);

        K = HID;
    }

    pool_bn_kernel<<<(M * 32 + 255) / 256, 256>>>(hA, batch, scale, shift, pooled, cnt, M);
    head_kernel<<<1, NGRAPH>>>(pooled, cnt, Wc, bc, out, mode);
}